// round 15
// baseline (speedup 1.0000x reference)
#include <cuda_runtime.h>
#include <math_constants.h>
#include <cfloat>

// Problem constants (B=2, L=256, A=12, C=32, K=30)
#define NB 2
#define NL 256
#define NA 12
#define NATOM 3072          // NL*NA
#define NROWS (NB*NATOM)    // 6144
#define NC 32
#define KNB 30
#define BIGD 1000000.0f
#define EMPTY_BITS 0xFFFFFFFFu
#define POISON 1.0e18f               // masked-atom coordinate (d2 -> 3e36 exactly)
#define FULL 0xffffffffu

#define HALF 1536            // candidates per half-warp
#define NTH 48               // candidate rounds per lane per half (1536/32)

// Output layout (all float32, concatenated in reference tuple order)
#define O_COORDS 0                       // (B, NATOM, 3)  -> 18432
#define O_MASK   (NB*NATOM*3)            // (B, NATOM)     -> 6144
#define O_ENC    (O_MASK + NB*NATOM)     // (B, NATOM, 32) -> 196608
#define O_DIST   (O_ENC + NB*NATOM*NC)   // (B, NATOM, 30) -> 184320
#define O_IDX    (O_DIST + NB*NATOM*KNB) // (B, NATOM, 30) -> 184320

#define ROWS_PB 4            // rows per block (2 warps per row)
#define THR 256

__device__ float4 g_atoms[NB * NATOM];   // poisoned {x,y,z,mask}, 98 KB
__device__ float  g_A[NB * NC];          // rstd * scale
__device__ float  g_B[NB * NC];          // shift - mean * rstd * scale
__device__ int    g_rows[NROWS];         // compacted: active rows first
__device__ int    g_nact;                // number of active rows

// ---------------------------------------------------------------------------
// Prep (light): 24 blocks poison atoms (1 atom/thread). Block 0 additionally
// does single-warp shfl-scan compaction and graph-norm coefs.
// ---------------------------------------------------------------------------
#define PREP_BLOCKS 24
__global__ void prep_kernel(const float* __restrict__ coords,
                            const int* __restrict__ mask,
                            const float* __restrict__ T,
                            const float* __restrict__ scale,
                            const float* __restrict__ shift) {
    int tid = threadIdx.x;     // 256

    {
        int a = blockIdx.x * 256 + tid;     // 24*256 = 6144 = NROWS
        int b = a / NATOM;
        int j = a - b * NATOM;
        int m = mask[b * NL + j / NA];
        float4 v;
        float x = coords[a * 3 + 0], y = coords[a * 3 + 1], z = coords[a * 3 + 2];
        v.x = m ? x : POISON;
        v.y = m ? y : POISON;
        v.z = m ? z : POISON;
        v.w = (float)m;
        g_atoms[a] = v;
    }

    if (blockIdx.x != 0) return;

    __shared__ float s_nm[NB];

    if (tid < 32) {
        int lane = tid;
        int mloc[16];
        int s = 0;
        #pragma unroll
        for (int i = 0; i < 16; ++i) { mloc[i] = mask[lane * 16 + i]; s += mloc[i]; }
        int incl = s;
        #pragma unroll
        for (int off = 1; off < 32; off <<= 1) {
            int v = __shfl_up_sync(FULL, incl, off);
            if (lane >= off) incl += v;
        }
        int nA  = __shfl_sync(FULL, incl, 31);
        int pre = incl - s;
        if (lane == 0)  g_nact = nA * NA;
        if (lane == 16) {                     // single writer for both slots
            s_nm[0] = (float)pre;
            s_nm[1] = (float)(nA - pre);
        }

        int r = lane * 16;
        #pragma unroll
        for (int i = 0; i < 16; ++i) {
            int m = mloc[i];
            int base = m ? (NA * pre) : (NA * (nA + (r - pre)));
            #pragma unroll
            for (int a = 0; a < NA; ++a) g_rows[base + a] = r * NA + a;
            pre += m;
            ++r;
        }
    }
    __syncthreads();

    if (tid < NB * NC) {
        int b = tid >> 5, c = tid & 31;
        float nm = s_nm[b];
        float colsum = 0.f, tv[NA];
        #pragma unroll
        for (int a = 0; a < NA; ++a) { tv[a] = T[a * NC + c]; colsum += tv[a]; }
        float cntA = nm * (float)NA;
        float cnt  = fmaxf(cntA, 1.0f);
        float mean = (nm * colsum) / cnt;
        float ssqm = 0.f;
        #pragma unroll
        for (int a = 0; a < NA; ++a) {
            float d = tv[a] - mean;
            ssqm = fmaf(d, d, ssqm);
        }
        float ssq  = nm * ssqm + ((float)NATOM - cntA) * mean * mean;
        float rstd = rsqrtf(ssq / cnt + 1e-5f);
        float Ac   = rstd * scale[c];
        g_A[tid] = Ac;
        g_B[tid] = shift[c] - mean * Ac;
    }
}

// ---------------------------------------------------------------------------
// Refill: k-th smallest of the 24-element sub-column [tb,tb+24) of column w
// (within this half's candidate range, offset base). q warp-uniform.
// ---------------------------------------------------------------------------
__device__ __forceinline__ void refill24(const float4* At, int lane, int base,
                                         int w, int tb, int k,
                                         float qx, float qy, float qz,
                                         unsigned &resv, int &resj) {
    unsigned k0; int j0;
    if (lane < 24) {
        int t = tb + lane;
        float4 a0 = __ldg(&At[base + t * 32 + w]);
        float dx = qx - a0.x, dy = qy - a0.y, dz = qz - a0.z;
        k0 = __float_as_uint(fmaf(dx, dx, fmaf(dy, dy, dz * dz)));
        j0 = base + t * 32 + w;
    } else { k0 = EMPTY_BITS; j0 = 0x7fffffff; }

    resv = EMPTY_BITS; resj = 0;
    for (int it = 0; it < k; ++it) {
        unsigned gm  = __reduce_min_sync(FULL, k0);
        unsigned gcj = (k0 == gm) ? (unsigned)j0 : 0xFFFFFFFFu;
        unsigned gj  = __reduce_min_sync(FULL, gcj);
        resv = gm; resj = (int)gj;
        if (j0 == (int)gj) k0 = EMPTY_BITS;
    }
}

// ---------------------------------------------------------------------------
// KNN: 2 warps per row. Warp h scans candidates [h*1536,(h+1)*1536) with dual
// depth-24 top-2 streams + extract-30; halves merged via merge-path ranks.
// ---------------------------------------------------------------------------
__global__ void __launch_bounds__(THR, 4)
knn_kernel(const float* __restrict__ coords,
           const float* __restrict__ T,
           float* __restrict__ out) {
    __shared__ unsigned s_val[ROWS_PB][2][32];
    __shared__ int      s_idx[ROWS_PB][2][32];

    int tid  = threadIdx.x;
    int warp = tid >> 5;
    int lane = tid & 31;
    int r    = warp >> 1;                 // row slot within block (0..3)
    int h    = warp & 1;                  // half (0/1)

    // coords copy + mask output, spread over grid threads
    {
        int i = blockIdx.x * THR + tid;
        if (i < NROWS * 3) out[O_COORDS + i] = coords[i];
        if (i < NROWS)     out[O_MASK + i] = g_atoms[i].w;
    }

    int slot = blockIdx.x * ROWS_PB + r;
    int row  = g_rows[slot];
    int b    = row / NATOM;
    int ib   = row - b * NATOM;
    bool active = (slot < g_nact);

    const float4* At = g_atoms + b * NATOM;

    if (active) {
        float4 q = __ldg(&At[ib]);

        if (h == 0) {                     // encode for active row
            int ty = ib % NA;
            out[O_ENC + row * NC + lane] =
                fmaf(__ldg(&T[ty * NC + lane]), g_A[b * NC + lane], g_B[b * NC + lane]);
        }

        int base = h * HALF;

        // ---- phase A: dual depth-24 branchless top-2 streams ----
        unsigned va0 = EMPTY_BITS, va1 = EMPTY_BITS, vb0 = EMPTY_BITS, vb1 = EMPTY_BITS;
        int ia0 = 0, ia1 = 0, ib0 = 0, ib1 = 0;

        #pragma unroll 8
        for (int t = 0; t < 24; ++t) {
            float4 a = __ldg(&At[base + t * 32 + lane]);
            float dx = q.x - a.x, dy = q.y - a.y, dz = q.z - a.z;
            unsigned kb = __float_as_uint(fmaf(dx, dx, fmaf(dy, dy, dz * dz)));
            int j = base + t * 32 + lane;
            bool lt1 = kb < va1;
            bool lt0 = kb < va0;          // strict < keeps lowest-index ties
            va1 = lt1 ? (lt0 ? va0 : kb) : va1;
            ia1 = lt1 ? (lt0 ? ia0 : j ) : ia1;
            va0 = lt0 ? kb : va0;
            ia0 = lt0 ? j  : ia0;
        }
        #pragma unroll 8
        for (int t = 24; t < NTH; ++t) {
            float4 a = __ldg(&At[base + t * 32 + lane]);
            float dx = q.x - a.x, dy = q.y - a.y, dz = q.z - a.z;
            unsigned kb = __float_as_uint(fmaf(dx, dx, fmaf(dy, dy, dz * dz)));
            int j = base + t * 32 + lane;
            bool lt1 = kb < vb1;
            bool lt0 = kb < vb0;
            vb1 = lt1 ? (lt0 ? vb0 : kb) : vb1;
            ib1 = lt1 ? (lt0 ? ib0 : j ) : ib1;
            vb0 = lt0 ? kb : vb0;
            ib0 = lt0 ? j  : ib0;
        }

        // ---- extract-min x30 within this half ----
        int cA = 0, cB = 0;
        unsigned rvb = EMPTY_BITS; int rj = 0;

        #pragma unroll 1
        for (int p = 0; p < KNB; ++p) {
            unsigned pv = (vb0 < va0) ? vb0 : va0;   // tie -> stream A (lower j)
            int      pi = (vb0 < va0) ? ib0 : ia0;

            unsigned mvb = __reduce_min_sync(FULL, pv);
            unsigned cj  = (pv == mvb) ? (unsigned)pi : 0xFFFFFFFFu;
            unsigned mj  = __reduce_min_sync(FULL, cj);
            if (lane == p) { rvb = mvb; rj = (int)mj; }

            if (p < KNB - 1) {
                int loc = (int)mj - base;
                int w   = loc & 31;
                int tm  = loc >> 5;
                bool fromA = (tm < 24);
                bool needRefill = false;
                if (lane == w) {
                    if (fromA) { va0 = va1; ia0 = ia1; va1 = EMPTY_BITS; ++cA;
                                 needRefill = (va0 == EMPTY_BITS); }
                    else       { vb0 = vb1; ib0 = ib1; vb1 = EMPTY_BITS; ++cB;
                                 needRefill = (vb0 == EMPTY_BITS); }
                }
                if (__ballot_sync(FULL, needRefill)) {
                    int k = __shfl_sync(FULL, fromA ? cA : cB, w) + 1;
                    unsigned resv; int resj;
                    refill24(At, lane, base, w, fromA ? 0 : 24, k,
                             q.x, q.y, q.z, resv, resj);
                    if (lane == w) {
                        if (fromA) { va0 = resv; ia0 = resj; }
                        else       { vb0 = resv; ib0 = resj; }
                    }
                }
            }
        }

        if (lane < KNB) {
            s_val[r][h][lane] = rvb;
            s_idx[r][h][lane] = rj;
        }
    }

    __syncthreads();

    if (!active) {                        // masked row -> constant outputs
        if (h == 0) {
            out[O_ENC + row * NC + lane] = 0.0f;
            if (lane < KNB) {
                out[O_DIST + row * KNB + lane] = BIGD;
                out[O_IDX  + row * KNB + lane] = 0.0f;
            }
        }
        return;
    }

    // ---- merge the two sorted 30-lists (h==0 warp) via merge-path ranks ----
    if (h == 0 && lane < KNB) {
        unsigned av = s_val[r][0][lane]; int aj = s_idx[r][0][lane];
        unsigned bv = s_val[r][1][lane]; int bj = s_idx[r][1][lane];

        // rankA = lane + |{B < A_lane}|  (strict lexicographic (v, j))
        int lo = 0, hi = KNB;
        while (lo < hi) {
            int mid = (lo + hi) >> 1;
            unsigned mv = s_val[r][1][mid]; int mj = s_idx[r][1][mid];
            bool less = (mv < av) || (mv == av && mj < aj);
            if (less) lo = mid + 1; else hi = mid;
        }
        int rankA = lane + lo;

        // rankB = lane + |{A < B_lane}|
        lo = 0; hi = KNB;
        while (lo < hi) {
            int mid = (lo + hi) >> 1;
            unsigned mv = s_val[r][0][mid]; int mj = s_idx[r][0][mid];
            bool less = (mv < bv) || (mv == bv && mj < bj);
            if (less) lo = mid + 1; else hi = mid;
        }
        int rankB = lane + lo;

        if (rankA < KNB) {
            float d2 = __uint_as_float(av);
            out[O_DIST + row * KNB + rankA] = (d2 > 1e30f) ? BIGD : sqrtf(d2 + 1e-6f);
            out[O_IDX  + row * KNB + rankA] = (float)aj;
        }
        if (rankB < KNB) {
            float d2 = __uint_as_float(bv);
            out[O_DIST + row * KNB + rankB] = (d2 > 1e30f) ? BIGD : sqrtf(d2 + 1e-6f);
            out[O_IDX  + row * KNB + rankB] = (float)bj;
        }
    }
}

// ---------------------------------------------------------------------------
extern "C" void kernel_launch(void* const* d_in, const int* in_sizes, int n_in,
                              void* d_out, int out_size) {
    const float* coords = (const float*)d_in[0];   // (2,256,12,3) f32
    const int*   mask   = (const int*)d_in[1];     // (2,256) i32
    const float* emb    = (const float*)d_in[2];   // (12,32) f32
    const float* scale  = (const float*)d_in[3];   // (1,1,32) f32
    const float* shift  = (const float*)d_in[4];   // (1,1,32) f32
    float* out = (float*)d_out;

    prep_kernel<<<PREP_BLOCKS, 256>>>(coords, mask, emb, scale, shift);

    int nblocks = NROWS / ROWS_PB;                 // 1536
    knn_kernel<<<nblocks, THR>>>(coords, emb, out);
}

// round 16
// speedup vs baseline: 1.5985x; 1.5985x over previous
#include <cuda_runtime.h>
#include <math_constants.h>
#include <cfloat>

// Problem constants (B=2, L=256, A=12, C=32, K=30)
#define NB 2
#define NL 256
#define NA 12
#define NATOM 3072          // NL*NA
#define NROWS (NB*NATOM)    // 6144
#define NC 32
#define KNB 30
#define BIGD 1000000.0f
#define EMPTY_BITS 0xFFFFFFFFu
#define POISON 1.0e18f               // masked-atom coordinate (d2 -> 3e36 exactly)
#define FULL 0xffffffffu

// Output layout (all float32, concatenated in reference tuple order)
#define O_COORDS 0                       // (B, NATOM, 3)  -> 18432
#define O_MASK   (NB*NATOM*3)            // (B, NATOM)     -> 6144
#define O_ENC    (O_MASK + NB*NATOM)     // (B, NATOM, 32) -> 196608
#define O_DIST   (O_ENC + NB*NATOM*NC)   // (B, NATOM, 30) -> 184320
#define O_IDX    (O_DIST + NB*NATOM*KNB) // (B, NATOM, 30) -> 184320

#define WARPS 4              // row slots per block (1 row per warp)
#define THR (WARPS * 32)     // 128

// Compacted per-batch atom table: actives first (ascending index), masked
// (poisoned coords) after. .w = atom index within batch, as float (exact).
__device__ float4 g_cat[NB * NATOM];
__device__ float  g_A[NB * NC];          // rstd * scale
__device__ float  g_B[NB * NC];          // shift - mean * rstd * scale
__device__ int    g_rows[NROWS];         // query compaction: active rows first
__device__ int    g_nact;                // active rows (global)
__device__ int    g_nactb[NB];           // active atoms per batch

// ---------------------------------------------------------------------------
// Prep: 24 blocks; EACH block recomputes the 512-residue mask scan in smem
// (cheap, no serial block-0 path), then places its 256 atoms into g_cat /
// g_rows. Block 0 additionally writes coefs and counters.
// ---------------------------------------------------------------------------
#define PREP_BLOCKS 24
__global__ void prep_kernel(const float* __restrict__ coords,
                            const int* __restrict__ mask,
                            const float* __restrict__ T,
                            const float* __restrict__ scale,
                            const float* __restrict__ shift) {
    __shared__ int s_mask[NB * NL];       // 512 residue masks
    __shared__ int s_lanepre[33];         // exclusive prefix per 16-residue lane

    int tid = threadIdx.x;                // 256

    if (tid < 32) {
        int mloc[16];
        int s = 0;
        #pragma unroll
        for (int i = 0; i < 16; ++i) {
            mloc[i] = mask[tid * 16 + i];
            s_mask[tid * 16 + i] = mloc[i];
            s += mloc[i];
        }
        int incl = s;
        #pragma unroll
        for (int off = 1; off < 32; off <<= 1) {
            int v = __shfl_up_sync(FULL, incl, off);
            if (tid >= off) incl += v;
        }
        s_lanepre[tid] = incl - s;        // exclusive prefix at residue tid*16
        if (tid == 31) s_lanepre[32] = incl;   // total active residues (global)
    }
    __syncthreads();

    int nAg = s_lanepre[32];
    int nA0 = s_lanepre[16];              // actives in residues [0,256) = batch 0
    int nA1 = nAg - nA0;

    if (blockIdx.x == 0) {
        if (tid == 0) {
            g_nact = nAg * NA;
            g_nactb[0] = nA0 * NA;
            g_nactb[1] = nA1 * NA;
        }
        if (tid < NB * NC) {              // graph-norm coefficients
            int b = tid >> 5, c = tid & 31;
            float nm = (float)(b ? nA1 : nA0);
            float colsum = 0.f, tv[NA];
            #pragma unroll
            for (int a = 0; a < NA; ++a) { tv[a] = T[a * NC + c]; colsum += tv[a]; }
            float cntA = nm * (float)NA;
            float cnt  = fmaxf(cntA, 1.0f);
            float mean = (nm * colsum) / cnt;
            float ssqm = 0.f;
            #pragma unroll
            for (int a = 0; a < NA; ++a) {
                float d = tv[a] - mean;
                ssqm = fmaf(d, d, ssqm);
            }
            float ssq  = nm * ssqm + ((float)NATOM - cntA) * mean * mean;
            float rstd = rsqrtf(ssq / cnt + 1e-5f);
            float Ac   = rstd * scale[c];
            g_A[tid] = Ac;
            g_B[tid] = shift[c] - mean * Ac;
        }
    }

    // ---- place this thread's atom ----
    int a  = blockIdx.x * 256 + tid;      // 0..6143 (global atom/row id)
    int b  = a / NATOM;
    int j  = a - b * NATOM;               // atom index within batch
    int rb = j / NA;                      // residue within batch
    int ty = j - rb * NA;
    int r  = b * NL + rb;                 // global residue
    int l  = r >> 4, loc = r & 15;
    int pre = s_lanepre[l];
    for (int i = 0; i < loc; ++i) pre += s_mask[l * 16 + i];   // global prefix
    int m = s_mask[r];

    int preB = pre - (b ? nA0 : 0);       // per-batch prefix
    int nAb  = b ? nA1 : nA0;
    int pos  = m ? (NA * preB + ty)
                 : (NA * (nAb + (rb - preB)) + ty);            // per-batch pos
    float x = coords[a * 3 + 0], y = coords[a * 3 + 1], z = coords[a * 3 + 2];
    float4 v;
    v.x = m ? x : POISON;
    v.y = m ? y : POISON;
    v.z = m ? z : POISON;
    v.w = (float)j;                       // exact (j < 3072)
    g_cat[b * NATOM + pos] = v;

    int slot = m ? (NA * pre + ty)
                 : (NA * (nAg + (r - pre)) + ty);              // global slot
    g_rows[slot] = a;
}

// ---------------------------------------------------------------------------
// Refill: k-th smallest over positions [t0,t1) of column w (lanes stride 32).
// Up to 3 rounds (t1-t0 <= 72 for stream B, 24 for stream A). q warp-uniform.
// ---------------------------------------------------------------------------
__device__ __forceinline__ void refillR(const float4* At, int lane, int w,
                                        int t0, int t1, int k,
                                        float qx, float qy, float qz,
                                        unsigned &resv, int &resj) {
    unsigned kv[3]; int kj[3];
    #pragma unroll
    for (int s = 0; s < 3; ++s) {
        int t = t0 + s * 32 + lane;
        if (t < t1) {
            float4 a = __ldg(&At[t * 32 + w]);
            float dx = qx - a.x, dy = qy - a.y, dz = qz - a.z;
            kv[s] = __float_as_uint(fmaf(dx, dx, fmaf(dy, dy, dz * dz)));
            kj[s] = t * 32 + w;
        } else { kv[s] = EMPTY_BITS; kj[s] = 0x7fffffff; }
    }
    resv = EMPTY_BITS; resj = 0;
    for (int it = 0; it < k; ++it) {
        unsigned lm = kv[0]; int lj = kj[0];     // strict < : lower s = lower pos
        if (kv[1] < lm) { lm = kv[1]; lj = kj[1]; }
        if (kv[2] < lm) { lm = kv[2]; lj = kj[2]; }
        unsigned gm  = __reduce_min_sync(FULL, lm);
        unsigned gcj = (lm == gm) ? (unsigned)lj : 0xFFFFFFFFu;
        unsigned gj  = __reduce_min_sync(FULL, gcj);
        resv = gm; resj = (int)gj;
        if (kj[0] == (int)gj) kv[0] = EMPTY_BITS;
        if (kj[1] == (int)gj) kv[1] = EMPTY_BITS;
        if (kj[2] == (int)gj) kv[2] = EMPTY_BITS;
    }
}

// ---------------------------------------------------------------------------
// KNN: warp-per-slot over compacted rows. Phase A scans ONLY ~nact_b
// candidates from the compacted table (~49 windows vs 96). Extraction =
// R13 engine on (key, position); real atom index recovered at the end.
// ---------------------------------------------------------------------------
__global__ void __launch_bounds__(THR, 8)
knn_kernel(const float* __restrict__ coords,
           const int* __restrict__ mask,
           const float* __restrict__ T,
           float* __restrict__ out) {
    int tid  = threadIdx.x;
    int warp = tid >> 5;
    int lane = tid & 31;

    // coords copy + mask output, grid-stride over spare threads
    {
        int i = blockIdx.x * THR + tid;
        if (i < NROWS * 3) out[O_COORDS + i] = coords[i];
        if (i < NROWS) {
            int bb = i / NATOM;
            int jj = i - bb * NATOM;
            out[O_MASK + i] = (float)mask[bb * NL + jj / NA];
        }
    }

    int slot = blockIdx.x * WARPS + warp;
    int row  = g_rows[slot];
    int b    = row / NATOM;

    float* dist_out = out + O_DIST + row * KNB;
    float* idx_out  = out + O_IDX  + row * KNB;

    if (slot >= g_nact) {                     // masked row -> constant outputs
        out[O_ENC + row * NC + lane] = 0.0f;
        if (lane < KNB) {
            dist_out[lane] = BIGD;
            idx_out[lane]  = 0.0f;
        }
        return;
    }

    int ib = row - b * NATOM;
    const float4* At = g_cat + b * NATOM;

    float qx = __ldg(&coords[row * 3 + 0]);
    float qy = __ldg(&coords[row * 3 + 1]);
    float qz = __ldg(&coords[row * 3 + 2]);

    // encode for active row
    {
        int ty = ib % NA;
        out[O_ENC + row * NC + lane] =
            fmaf(__ldg(&T[ty * NC + lane]), g_A[b * NC + lane], g_B[b * NC + lane]);
    }

    int nact_b = g_nactb[b];
    int Tn = ((nact_b + 31) >> 5) + 1;        // +1 poisoned window (nact<30 case)
    if (Tn > 96) Tn = 96;

    // ---- phase A: two branchless top-2 streams per lane (A: t<24, B: t>=24)
    unsigned va0 = EMPTY_BITS, va1 = EMPTY_BITS, vb0 = EMPTY_BITS, vb1 = EMPTY_BITS;
    int ia0 = 0, ia1 = 0, ib0 = 0, ib1 = 0;

    int tA = (Tn < 24) ? Tn : 24;
    #pragma unroll 4
    for (int t = 0; t < tA; ++t) {
        float4 a = __ldg(&At[t * 32 + lane]);
        float dx = qx - a.x, dy = qy - a.y, dz = qz - a.z;
        unsigned kb = __float_as_uint(fmaf(dx, dx, fmaf(dy, dy, dz * dz)));
        int j = t * 32 + lane;                // list position (monotone in idx)
        bool lt1 = kb < va1;
        bool lt0 = kb < va0;                  // strict < keeps lowest-pos ties
        va1 = lt1 ? (lt0 ? va0 : kb) : va1;
        ia1 = lt1 ? (lt0 ? ia0 : j ) : ia1;
        va0 = lt0 ? kb : va0;
        ia0 = lt0 ? j  : ia0;
    }
    #pragma unroll 4
    for (int t = 24; t < Tn; ++t) {
        float4 a = __ldg(&At[t * 32 + lane]);
        float dx = qx - a.x, dy = qy - a.y, dz = qz - a.z;
        unsigned kb = __float_as_uint(fmaf(dx, dx, fmaf(dy, dy, dz * dz)));
        int j = t * 32 + lane;
        bool lt1 = kb < vb1;
        bool lt0 = kb < vb0;
        vb1 = lt1 ? (lt0 ? vb0 : kb) : vb1;
        ib1 = lt1 ? (lt0 ? ib0 : j ) : ib1;
        vb0 = lt0 ? kb : vb0;
        ib0 = lt0 ? j  : ib0;
    }

    // ---- extract-min x30 from the 32 lane-heads ----
    int cA = 0, cB = 0;
    unsigned rvb = EMPTY_BITS; int rj = 0;    // lane p holds pass-p result

    #pragma unroll 1
    for (int p = 0; p < KNB; ++p) {
        unsigned pv = (vb0 < va0) ? vb0 : va0;   // tie -> stream A (lower pos)
        int      pi = (vb0 < va0) ? ib0 : ia0;

        unsigned mvb = __reduce_min_sync(FULL, pv);
        unsigned cj  = (pv == mvb) ? (unsigned)pi : 0xFFFFFFFFu;
        unsigned mj  = __reduce_min_sync(FULL, cj);
        if (lane == p) { rvb = mvb; rj = (int)mj; }

        if (p < KNB - 1) {
            int w  = (int)(mj & 31u);
            int tm = (int)(mj >> 5);
            bool fromA = (tm < 24);
            bool needRefill = false;
            if (lane == w) {
                if (fromA) { va0 = va1; ia0 = ia1; va1 = EMPTY_BITS; ++cA;
                             needRefill = (va0 == EMPTY_BITS); }
                else       { vb0 = vb1; ib0 = ib1; vb1 = EMPTY_BITS; ++cB;
                             needRefill = (vb0 == EMPTY_BITS); }
            }
            if (__ballot_sync(FULL, needRefill)) {
                int k = __shfl_sync(FULL, fromA ? cA : cB, w) + 1;
                int t0 = fromA ? 0 : 24;
                int t1 = fromA ? tA : Tn;
                unsigned resv; int resj;
                refillR(At, lane, w, t0, t1, k, qx, qy, qz, resv, resj);
                if (lane == w) {
                    if (fromA) { va0 = resv; ia0 = resj; }
                    else       { vb0 = resv; ib0 = resj; }
                }
            }
        }
    }

    if (lane < KNB) {
        float d2 = __uint_as_float(rvb);
        float dv = (d2 > 1e30f) ? BIGD : sqrtf(d2 + 1e-6f);
        dist_out[lane] = dv;
        idx_out[lane]  = __ldg(&At[rj]).w;    // real atom index (exact float)
    }
}

// ---------------------------------------------------------------------------
extern "C" void kernel_launch(void* const* d_in, const int* in_sizes, int n_in,
                              void* d_out, int out_size) {
    const float* coords = (const float*)d_in[0];   // (2,256,12,3) f32
    const int*   mask   = (const int*)d_in[1];     // (2,256) i32
    const float* emb    = (const float*)d_in[2];   // (12,32) f32
    const float* scale  = (const float*)d_in[3];   // (1,1,32) f32
    const float* shift  = (const float*)d_in[4];   // (1,1,32) f32
    float* out = (float*)d_out;

    prep_kernel<<<PREP_BLOCKS, 256>>>(coords, mask, emb, scale, shift);

    int nblocks = NROWS / WARPS;                   // 1536
    knn_kernel<<<nblocks, THR>>>(coords, mask, emb, out);
}